// round 16
// baseline (speedup 1.0000x reference)
#include <cuda_runtime.h>
#include <cuda_fp16.h>
#include <math.h>
#include <stdint.h>

#define LSEQ   128
#define BATCH  8
#define CH     8
#define HID    256
#define NHEAD  8
#define DHEAD  32
#define FFD    1024
#define MAXPADC 15
#define NSEQ   1024

#define MB0 2368
#define MB1 1088
#define MC0 18944
#define MC1 8704
#define MTOT 27648

__device__ __half  g_winh[147456];
__device__ float   g_tokens[294912];
__device__ float   g_seq[MTOT * 256];
__device__ __half  g_qkvh[MTOT * 768];
__device__ __half  g_s2h[MTOT * 256];
__device__ __half  g_ffh[MTOT * 1024];
__device__ __half  g_combh[1024 * 512];
__device__ __half  g_wth[1818624];
__device__ float   g_bqkv[1536];

__device__ __forceinline__ float gelu_exact(float x) {
    return 0.5f * x * (1.0f + erff(x * 0.7071067811865476f));
}
__device__ __forceinline__ uint32_t smem_u32(const void* p) {
    uint32_t a;
    asm("{ .reg .u64 t; cvta.to.shared.u64 t, %1; cvt.u32.u64 %0, t; }" : "=r"(a) : "l"(p));
    return a;
}
__device__ __forceinline__ void cp16(uint32_t dst, const void* src) {
    asm volatile("cp.async.cg.shared.global [%0], [%1], 16;" :: "r"(dst), "l"(src));
}
__device__ __forceinline__ void cp_commit() {
    asm volatile("cp.async.commit_group;" ::: "memory");
}
template<int N>
__device__ __forceinline__ void cp_wait() {
    asm volatile("cp.async.wait_group %0;" :: "n"(N) : "memory");
}
__device__ __forceinline__ void mma_f16(float* c, const uint32_t* a,
                                        uint32_t b0, uint32_t b1) {
    asm volatile(
        "mma.sync.aligned.m16n8k16.row.col.f32.f16.f16.f32 "
        "{%0,%1,%2,%3}, {%4,%5,%6,%7}, {%8,%9}, {%0,%1,%2,%3};\n"
        : "+f"(c[0]), "+f"(c[1]), "+f"(c[2]), "+f"(c[3])
        : "r"(a[0]), "r"(a[1]), "r"(a[2]), "r"(a[3]), "r"(b0), "r"(b1));
}
__device__ __forceinline__ void ldsm4(uint32_t& r0, uint32_t& r1, uint32_t& r2,
                                      uint32_t& r3, uint32_t addr) {
    asm volatile("ldmatrix.sync.aligned.m8n8.x4.shared.b16 {%0,%1,%2,%3}, [%4];"
                 : "=r"(r0), "=r"(r1), "=r"(r2), "=r"(r3) : "r"(addr));
}
template<int SCALE>
__device__ __forceinline__ int nfun(int t) {
    return SCALE == 0 ? ((t + 8) >> 2) + 1 : (t >> 3) + 1;
}
template<int SCALE>
__device__ __forceinline__ int Sfun(int t) {
    if (SCALE == 0) {
        int m = t + 8, q = m >> 2, r = m & 3;
        return t + 2 * q * (q - 1) + r * q - 4;
    } else {
        int q = t >> 3, r = t & 7;
        return t + 4 * q * (q - 1) + r * q;
    }
}

#define NJOBS 16
struct WtJobs {
    const float* src[NJOBS];
    __half*      dst[NJOBS];
    int K[NJOBS], N[NJOBS], t0[NJOBS];
};
__global__ void wt_fused(WtJobs jobs, int njobs) {
    __shared__ float t[32][33];
    int tile = blockIdx.x;
    int ji = 0;
    #pragma unroll 1
    while (ji + 1 < njobs && tile >= jobs.t0[ji + 1]) ji++;
    int lt = tile - jobs.t0[ji];
    int K = jobs.K[ji], N = jobs.N[ji];
    int tn = N >> 5;
    int nb = (lt % tn) * 32, kb = (lt / tn) * 32;
    const float* W = jobs.src[ji];
    __half* WT = jobs.dst[ji];
    int tx = threadIdx.x & 31, ty = threadIdx.x >> 5;
    #pragma unroll
    for (int i = 0; i < 32; i += 8)
        t[ty + i][tx] = W[(size_t)(kb + ty + i) * N + nb + tx];
    __syncthreads();
    #pragma unroll
    for (int i = 0; i < 32; i += 8)
        WT[(size_t)(nb + ty + i) * K + kb + tx] = __float2half_rn(t[tx][ty + i]);
}

__global__ void win_kernel(const float* __restrict__ x, __half* __restrict__ win,
                           int E, int pl) {
    int plc = pl * CH;
    int tot = BATCH * E * plc;
    int idx = blockIdx.x * blockDim.x + threadIdx.x;
    if (idx >= tot) return;
    int r = idx % plc;
    int e = (idx / plc) % E;
    int b = idx / (plc * E);
    int p = r >> 3, c = r & 7;
    int i = e + p;
    win[idx] = __float2half_rn((i < MAXPADC) ? 0.0f : x[(b * LSEQ + (i - MAXPADC)) * CH + c]);
}

template<int SCALE>
__global__ void build_seq_ln(const float* __restrict__ tokens,
                             const float* __restrict__ pos,
                             const float* __restrict__ lg, const float* __restrict__ lb,
                             float* __restrict__ seq, __half* __restrict__ s2h,
                             int NMAX, int E, int pl, int st, int MBc, int rowoff) {
    int wid = threadIdx.x >> 5, lane = threadIdx.x & 31;
    int wg = blockIdx.x * 8 + wid;
    if (wg >= NSEQ * NMAX) return;
    int k = wg % NMAX, bt = wg / NMAX;
    int t = bt & (LSEQ - 1), b = bt >> 7;
    int n = nfun<SCALE>(t);
    if (k >= n) return;
    int ends = t + MAXPADC - (n - 1) * st + k * st;
    int j = ends - (pl - 1);
    j = j < 0 ? 0 : (j > E - 1 ? E - 1 : j);
    int m = rowoff + b * MBc + Sfun<SCALE>(t) + k;

    const float4* tp = (const float4*)(tokens + (size_t)(b * E + j) * 256) + lane * 2;
    const float4* pp = (const float4*)(pos + k * 256) + lane * 2;
    float4 t0 = tp[0], t1 = tp[1], p0 = pp[0], p1 = pp[1];
    float v[8] = { t0.x + p0.x, t0.y + p0.y, t0.z + p0.z, t0.w + p0.w,
                   t1.x + p1.x, t1.y + p1.y, t1.z + p1.z, t1.w + p1.w };
    float s = 0.0f, q = 0.0f;
    #pragma unroll
    for (int i = 0; i < 8; i++) { s += v[i]; q += v[i] * v[i]; }
    #pragma unroll
    for (int o = 16; o > 0; o >>= 1) {
        s += __shfl_xor_sync(0xffffffffu, s, o);
        q += __shfl_xor_sync(0xffffffffu, q, o);
    }
    float mu = s * (1.0f / 256.0f);
    float var = q * (1.0f / 256.0f) - mu * mu;
    float rinv = rsqrtf(var + 1e-5f);

    float4* sp = (float4*)(seq + (size_t)m * 256) + lane * 2;
    sp[0] = make_float4(v[0], v[1], v[2], v[3]);
    sp[1] = make_float4(v[4], v[5], v[6], v[7]);

    const float4* gp = (const float4*)(lg) + lane * 2;
    const float4* bp = (const float4*)(lb) + lane * 2;
    float4 g0 = gp[0], g1 = gp[1], bb0 = bp[0], bb1 = bp[1];
    __half2 h[4];
    h[0] = __floats2half2_rn((v[0]-mu)*rinv*g0.x+bb0.x, (v[1]-mu)*rinv*g0.y+bb0.y);
    h[1] = __floats2half2_rn((v[2]-mu)*rinv*g0.z+bb0.z, (v[3]-mu)*rinv*g0.w+bb0.w);
    h[2] = __floats2half2_rn((v[4]-mu)*rinv*g1.x+bb1.x, (v[5]-mu)*rinv*g1.y+bb1.y);
    h[3] = __floats2half2_rn((v[6]-mu)*rinv*g1.z+bb1.z, (v[7]-mu)*rinv*g1.w+bb1.w);
    *(uint4*)(s2h + (size_t)m * 256 + lane * 8) = *(uint4*)h;
}

__global__ void gather2_kernel(const float* __restrict__ seq, __half* __restrict__ comb) {
    int idx = blockIdx.x * blockDim.x + threadIdx.x;
    if (idx >= 2 * NSEQ * HID) return;
    int scale = idx >= NSEQ * HID;
    int id2 = idx - scale * NSEQ * HID;
    int h = id2 & 255;
    int bt = id2 >> 8;
    int t = bt & (LSEQ - 1);
    int b = bt >> 7;
    int m;
    if (!scale) {
        int n = nfun<0>(t);
        m = b * MB0 + Sfun<0>(t) + n - 1;
    } else {
        int n = nfun<1>(t);
        m = MC0 + b * MB1 + Sfun<1>(t) + n - 1;
    }
    comb[bt * 512 + scale * 256 + h] = __float2half_rn(seq[(size_t)m * HID + h]);
}

__global__ void ln_final(const float* __restrict__ in, const float* __restrict__ g,
                         const float* __restrict__ b, float* __restrict__ out) {
    int warp = threadIdx.x >> 5, lane = threadIdx.x & 31;
    size_t row = (size_t)blockIdx.x * 8 + warp;
    const float4* p = (const float4*)(in + row * 256);
    float4 v0 = p[lane], v1 = p[lane + 32];
    float s = v0.x + v0.y + v0.z + v0.w + v1.x + v1.y + v1.z + v1.w;
    #pragma unroll
    for (int o = 16; o > 0; o >>= 1) s += __shfl_xor_sync(0xffffffffu, s, o);
    float mu = s * (1.0f / 256.0f);
    float d0x = v0.x - mu, d0y = v0.y - mu, d0z = v0.z - mu, d0w = v0.w - mu;
    float d1x = v1.x - mu, d1y = v1.y - mu, d1z = v1.z - mu, d1w = v1.w - mu;
    float q = d0x*d0x + d0y*d0y + d0z*d0z + d0w*d0w
            + d1x*d1x + d1y*d1y + d1z*d1z + d1w*d1w;
    #pragma unroll
    for (int o = 16; o > 0; o >>= 1) q += __shfl_xor_sync(0xffffffffu, q, o);
    float r = rsqrtf(q * (1.0f / 256.0f) + 1e-5f);
    const float4* gp = (const float4*)g;
    const float4* bp = (const float4*)b;
    float4 g0 = gp[lane], g1 = gp[lane + 32];
    float4 b0 = bp[lane], b1 = bp[lane + 32];
    float4* po = (float4*)(out + row * 256);
    po[lane]      = make_float4(d0x*r*g0.x+b0.x, d0y*r*g0.y+b0.y, d0z*r*g0.z+b0.z, d0w*r*g0.w+b0.w);
    po[lane + 32] = make_float4(d1x*r*g1.x+b1.x, d1y*r*g1.y+b1.y, d1z*r*g1.z+b1.z, d1w*r*g1.w+b1.w);
}

#define HSTAGE 12288
#define HSMEM  (3 * HSTAGE * 2)
template<int EPI>
__global__ void __launch_bounds__(512, 1) hgemm_kernel(
        const __half* __restrict__ A, const __half* __restrict__ BT,
        const float* __restrict__ bias, void* __restrict__ Cv,
        int N, int K) {
    extern __shared__ __half sm[];
    const uint32_t sb = smem_u32(sm);
    const int tid = threadIdx.x, lane = tid & 31, warp = tid >> 5;
    const int bm = blockIdx.y << 7, bn = blockIdx.x << 8;
    const int wm = (warp & 3) << 5;
    const int wn = (warp >> 2) << 6;
    const int nc = K >> 5;

    float acc[2][8][4];
    #pragma unroll
    for (int mi = 0; mi < 2; mi++)
        #pragma unroll
        for (int j = 0; j < 8; j++)
            #pragma unroll
            for (int q = 0; q < 4; q++) acc[mi][j][q] = 0.0f;

    auto issue = [&](int c) {
        const int koff = c << 5;
        const uint32_t stg = sb + (uint32_t)((c % 3) * HSTAGE) * 2u;
        {
            int row = tid >> 2, sc = tid & 3;
            uint32_t dst = stg + (uint32_t)(row * 32 + ((sc ^ ((row >> 1) & 3)) << 3)) * 2u;
            cp16(dst, A + (size_t)(bm + row) * K + koff + sc * 8);
        }
        #pragma unroll
        for (int i = 0; i < 2; i++) {
            int seg = tid + i * 512;
            int row = seg >> 2, sc = seg & 3;
            uint32_t dst = stg + (uint32_t)(4096 + row * 32 + ((sc ^ ((row >> 1) & 3)) << 3)) * 2u;
            cp16(dst, BT + (size_t)(bn + row) * K + koff + sc * 8);
        }
    };

    #pragma unroll
    for (int s = 0; s < 2; s++) {
        if (s < nc) issue(s);
        cp_commit();
    }

    const int r_lo = lane >> 2, wv = lane & 3;
    const int arow = wm + (lane & 15);
    const int asel = (lane >> 4) & 1;
    int brow[4], bsel[4];
    {
        int i = lane >> 3;
        #pragma unroll
        for (int g = 0; g < 4; g++) {
            brow[g] = wn + ((g << 1) + (i >> 1)) * 8 + (lane & 7);
            bsel[g] = i & 1;
        }
    }

    for (int c = 0; c < nc; c++) {
        cp_wait<1>();
        __syncthreads();
        if (c + 2 < nc) issue(c + 2);
        cp_commit();

        const uint32_t stA = sb + (uint32_t)((c % 3) * HSTAGE) * 2u;
        const uint32_t stB = stA + 8192u;
        #pragma unroll
        for (int kk = 0; kk < 2; kk++) {
            uint32_t a[2][4];
            #pragma unroll
            for (int mi = 0; mi < 2; mi++) {
                int r = arow + mi * 16;
                uint32_t ad = stA + (uint32_t)(r * 64 + ((((kk << 1) | asel) ^ ((r >> 1) & 3)) << 4));
                ldsm4(a[mi][0], a[mi][1], a[mi][2], a[mi][3], ad);
            }
            uint32_t bf[8][2];
            #pragma unroll
            for (int g = 0; g < 4; g++) {
                int r = brow[g];
                uint32_t bd = stB + (uint32_t)(r * 64 + ((((kk << 1) | bsel[g]) ^ ((r >> 1) & 3)) << 4));
                ldsm4(bf[2*g][0], bf[2*g][1], bf[2*g+1][0], bf[2*g+1][1], bd);
            }
            #pragma unroll
            for (int j = 0; j < 8; j++)
                #pragma unroll
                for (int mi = 0; mi < 2; mi++)
                    mma_f16(acc[mi][j], a[mi], bf[j][0], bf[j][1]);
        }
    }

    #pragma unroll
    for (int mi = 0; mi < 2; mi++) {
        const int r = bm + wm + mi * 16 + r_lo;
        #pragma unroll
        for (int j = 0; j < 8; j++) {
            const int cl = bn + wn + j * 8 + wv * 2;
            float bf0 = bias[cl], bf1 = bias[cl + 1];
            float v0 = acc[mi][j][0] + bf0, v1 = acc[mi][j][1] + bf1;
            float v2 = acc[mi][j][2] + bf0, v3 = acc[mi][j][3] + bf1;
            if (EPI == 0) {
                float* C = (float*)Cv;
                *(float2*)(C + (size_t)r * N + cl)       = make_float2(v0, v1);
                *(float2*)(C + (size_t)(r + 8) * N + cl) = make_float2(v2, v3);
            } else if (EPI == 1) {
                __half* C = (__half*)Cv;
                *(__half2*)(C + (size_t)r * N + cl) =
                    __floats2half2_rn(gelu_exact(v0), gelu_exact(v1));
                *(__half2*)(C + (size_t)(r + 8) * N + cl) =
                    __floats2half2_rn(gelu_exact(v2), gelu_exact(v3));
            } else {
                __half* C = (__half*)Cv;
                *(__half2*)(C + (size_t)r * N + cl)       = __floats2half2_rn(v0, v1);
                *(__half2*)(C + (size_t)(r + 8) * N + cl) = __floats2half2_rn(v2, v3);
            }
        }
    }
}

#define H64STAGE 10240
#define H64SMEM  (3 * H64STAGE * 2)
template<int EPI>
__global__ void __launch_bounds__(512, 1) hgemm64_kernel(
        const __half* __restrict__ A, const __half* __restrict__ BT,
        const float* __restrict__ bias, float* __restrict__ C,
        int K,
        const float* __restrict__ lng, const float* __restrict__ lnb,
        __half* __restrict__ lnout) {
    extern __shared__ __half sm[];
    const uint32_t sb = smem_u32(sm);
    const int tid = threadIdx.x, lane = tid & 31, warp = tid >> 5;
    const int bm = blockIdx.y << 6;
    const int wm = (warp & 1) << 5;
    const int wn = (warp >> 1) << 5;
    const int nc = K >> 5;

    float acc[2][4][4];
    #pragma unroll
    for (int mi = 0; mi < 2; mi++)
        #pragma unroll
        for (int j = 0; j < 4; j++)
            #pragma unroll
            for (int q = 0; q < 4; q++) acc[mi][j][q] = 0.0f;

    auto issue = [&](int c) {
        const int koff = c << 5;
        const uint32_t stg = sb + (uint32_t)((c % 3) * H64STAGE) * 2u;
        if (tid < 256) {
            int row = tid >> 2, sc = tid & 3;
            uint32_t dst = stg + (uint32_t)(row * 32 + ((sc ^ ((row >> 1) & 3)) << 3)) * 2u;
            cp16(dst, A + (size_t)(bm + row) * K + koff + sc * 8);
        }
        #pragma unroll
        for (int i = 0; i < 2; i++) {
            int seg = tid + i * 512;
            int row = seg >> 2, sc = seg & 3;
            uint32_t dst = stg + (uint32_t)(2048 + row * 32 + ((sc ^ ((row >> 1) & 3)) << 3)) * 2u;
            cp16(dst, BT + (size_t)row * K + koff + sc * 8);
        }
    };

    #pragma unroll
    for (int s = 0; s < 2; s++) {
        if (s < nc) issue(s);
        cp_commit();
    }

    const int r_lo = lane >> 2, wv = lane & 3;
    const int arow = wm + (lane & 15);
    const int asel = (lane >> 4) & 1;
    int brow[2], bsel2;
    {
        int i = lane >> 3;
        bsel2 = i & 1;
        #pragma unroll
        for (int g = 0; g < 2; g++)
            brow[g] = wn + ((g << 1) + (i >> 1)) * 8 + (lane & 7);
    }

    for (int c = 0; c < nc; c++) {
        cp_wait<1>();
        __syncthreads();
        if (c + 2 < nc) issue(c + 2);
        cp_commit();

        const uint32_t stA = sb + (uint32_t)((c % 3) * H64STAGE) * 2u;
        const uint32_t stB = stA + 4096u;
        #pragma unroll
        for (int kk = 0; kk < 2; kk++) {
            uint32_t a[2][4];
            #pragma unroll
            for (int mi = 0; mi < 2; mi++) {
                int r = arow + mi * 16;
                uint32_t ad = stA + (uint32_t)(r * 64 + ((((kk << 1) | asel) ^ ((r >> 1) & 3)) << 4));
                ldsm4(a[mi][0], a[mi][1], a[mi][2], a[mi][3], ad);
            }
            uint32_t bf[4][2];
            #pragma unroll
            for (int g = 0; g < 2; g++) {
                int r = brow[g];
                uint32_t bd = stB + (uint32_t)(r * 64 + ((((kk << 1) | bsel2) ^ ((r >> 1) & 3)) << 4));
                ldsm4(bf[2*g][0], bf[2*g][1], bf[2*g+1][0], bf[2*g+1][1], bd);
            }
            #pragma unroll
            for (int j = 0; j < 4; j++)
                #pragma unroll
                for (int mi = 0; mi < 2; mi++)
                    mma_f16(acc[mi][j], a[mi], bf[j][0], bf[j][1]);
        }
    }

    #pragma unroll
    for (int mi = 0; mi < 2; mi++) {
        const int r = bm + wm + mi * 16 + r_lo;
        #pragma unroll
        for (int j = 0; j < 4; j++) {
            const int cl = wn + j * 8 + wv * 2;
            float bf0 = bias[cl], bf1 = bias[cl + 1];
            float2* p0 = (float2*)(C + (size_t)r * 256 + cl);
            float2* p1 = (float2*)(C + (size_t)(r + 8) * 256 + cl);
            float2 o0 = *p0, o1 = *p1;
            acc[mi][j][0] += bf0 + o0.x; acc[mi][j][1] += bf1 + o0.y;
            acc[mi][j][2] += bf0 + o1.x; acc[mi][j][3] += bf1 + o1.y;
            *p0 = make_float2(acc[mi][j][0], acc[mi][j][1]);
            *p1 = make_float2(acc[mi][j][2], acc[mi][j][3]);
        }
    }
    if (EPI == 2) return;

    float2* red = (float2*)sm;
    float sums[4], sqs[4];
    #pragma unroll
    for (int mi = 0; mi < 2; mi++) {
        #pragma unroll
        for (int rr = 0; rr < 2; rr++) {
            float s = 0.0f, q = 0.0f;
            #pragma unroll
            for (int j = 0; j < 4; j++) {
                float v0 = acc[mi][j][rr * 2], v1 = acc[mi][j][rr * 2 + 1];
                s += v0 + v1; q += v0 * v0 + v1 * v1;
            }
            s += __shfl_xor_sync(0xffffffffu, s, 1);
            s += __shfl_xor_sync(0xffffffffu, s, 2);
            q += __shfl_xor_sync(0xffffffffu, q, 1);
            q += __shfl_xor_sync(0xffffffffu, q, 2);
            sums[mi * 2 + rr] = s; sqs[mi * 2 + rr] = q;
        }
    }
    const int wn_i = warp >> 1;
    __syncthreads();
    if (wv == 0) {
        #pragma unroll
        for (int idx = 0; idx < 4; idx++) {
            int rl = wm + (idx >> 1) * 16 + r_lo + (idx & 1) * 8;
            red[rl * 8 + wn_i] = make_float2(sums[idx], sqs[idx]);
        }
    }
    __syncthreads();
    float mus[4], rinvs[4];
    #pragma unroll
    for (int idx = 0; idx < 4; idx++) {
        int rl = wm + (idx >> 1) * 16 + r_lo + (idx & 1) * 8;
        float S = 0.0f, Q = 0.0f;
        #pragma unroll
        for (int w = 0; w < 8; w++) {
            float2 e = red[rl * 8 + w];
            S += e.x; Q += e.y;
        }
        float mu = S * (1.0f / 256.0f);
        mus[idx] = mu;
        rinvs[idx] = rsqrtf(Q * (1.0f / 256.0f) - mu * mu + 1e-5f);
    }
    #pragma unroll
    for (int mi = 0; mi < 2; mi++) {
        const int r = bm + wm + mi * 16 + r_lo;
        #pragma unroll
        for (int j = 0; j < 4; j++) {
            const int cl = wn + j * 8 + wv * 2;
            float gg0 = lng[cl], gg1 = lng[cl + 1];
            float bb0 = lnb[cl], bb1 = lnb[cl + 1];
            float mu0 = mus[mi * 2], ri0 = rinvs[mi * 2];
            float mu1 = mus[mi * 2 + 1], ri1 = rinvs[mi * 2 + 1];
            *(__half2*)(lnout + (size_t)r * 256 + cl) =
                __floats2half2_rn((acc[mi][j][0] - mu0) * ri0 * gg0 + bb0,
                                  (acc[mi][j][1] - mu0) * ri0 * gg1 + bb1);
            *(__half2*)(lnout + (size_t)(r + 8) * 256 + cl) =
                __floats2half2_rn((acc[mi][j][2] - mu1) * ri1 * gg0 + bb0,
                                  (acc[mi][j][3] - mu1) * ri1 * gg1 + bb1);
        }
    }
}

// ---- attention: one block per (scale,b,t); 288 threads = 34 queries x 8 heads ----
// dynamic smem: Ks[34][264] + Vs[34][264] fp32 (per-head stride 33, conflict-free)
#define ATT_SMEM (2 * 34 * 264 * 4)
__global__ void __launch_bounds__(288, 1) attn2_kernel(
        const __half* __restrict__ QKV, __half* __restrict__ O) {
    extern __shared__ float asmem[];
    float* Ks = asmem;
    float* Vs = asmem + 34 * 264;
    int bid = blockIdx.x;                  // 0..2047
    int scale = bid >> 10;
    int bt = bid & 1023;
    int t = bt & (LSEQ - 1), b = bt >> 7;
    int n, rb;
    if (scale == 0) { n = nfun<0>(t); rb = b * MB0 + Sfun<0>(t); }
    else            { n = nfun<1>(t); rb = MC0 + b * MB1 + Sfun<1>(t); }
    size_t base = (size_t)rb * 768;

    int tot = n << 7;                      // n * 128 half2 per array
    for (int i = threadIdx.x; i < tot; i += 288) {
        int kk = i >> 7, d = (i & 127) << 1;
        float2 kv = __half22float2(*(const __half2*)(QKV + base + (size_t)kk * 768 + 256 + d));
        float2 vv = __half22float2(*(const __half2*)(QKV + base + (size_t)kk * 768 + 512 + d));
        int off = kk * 264 + (d >> 5) * 33 + (d & 31);
        Ks[off] = kv.x; Ks[off + 1] = kv.y;
        Vs[off] = vv.x; Vs[off + 1] = vv.y;
    }
    __syncthreads();

    int tq = threadIdx.x >> 3, head = threadIdx.x & 7;
    if (tq < n) {
        const int hb = head * 33;
        float qr[32];
        #pragma unroll
        for (int d = 0; d < 32; d += 2) {
            float2 qv = __half22float2(*(const __half2*)(QKV + base + (size_t)tq * 768 + head * DHEAD + d));
            qr[d] = qv.x; qr[d + 1] = qv.y;
        }
        float sc[34];
        float mx = -1e30f;
        #pragma unroll
        for (int kk = 0; kk < 34; kk++) {
            float s = 0.0f;
            const float* kp = Ks + kk * 264 + hb;
            #pragma unroll
            for (int d = 0; d < 32; d++) s += qr[d] * kp[d];
            s *= 0.17677669529663687f;
            sc[kk] = (kk < n) ? s : -1e30f;
            mx = fmaxf(mx, sc[kk]);
        }
        float ssum = 0.0f;
        #pragma unroll
        for (int kk = 0; kk < 34; kk++) {
            float e = (kk < n) ? expf(sc[kk] - mx) : 0.0f;
            sc[kk] = e;
            ssum += e;
        }
        float inv = 1.0f / ssum;
        __half* op = O + (size_t)(rb + tq) * HID + head * DHEAD;
        #pragma unroll
        for (int d = 0; d < 32; d += 2) {
            float o0 = 0.0f, o1 = 0.0f;
            #pragma unroll
            for (int kk = 0; kk < 34; kk++) {
                const float* vp = Vs + kk * 264 + hb;
                o0 += sc[kk] * vp[d];
                o1 += sc[kk] * vp[d + 1];
            }
            *(__half2*)(op + d) = __floats2half2_rn(o0 * inv, o1 * inv);
        }
    }
}

static inline void gemm(const __half* A, const __half* WT, const float* bias, void* C,
                        int Mp, int N, int K, int epi) {
    dim3 grid(N >> 8, Mp >> 7), block(512);
    if (epi == 0)      hgemm_kernel<0><<<grid, block, HSMEM>>>(A, WT, bias, C, N, K);
    else if (epi == 1) hgemm_kernel<1><<<grid, block, HSMEM>>>(A, WT, bias, C, N, K);
    else               hgemm_kernel<4><<<grid, block, HSMEM>>>(A, WT, bias, C, N, K);
}
static inline void gemm64(const __half* A, const __half* WT, const float* bias, float* C,
                          int Mp, int K, int epi,
                          const float* lng = nullptr, const float* lnb = nullptr,
                          __half* lnout = nullptr) {
    dim3 grid(1, Mp >> 6), block(512);
    if (epi == 2) hgemm64_kernel<2><<<grid, block, H64SMEM>>>(A, WT, bias, C, K, lng, lnb, lnout);
    else          hgemm64_kernel<3><<<grid, block, H64SMEM>>>(A, WT, bias, C, K, lng, lnb, lnout);
}

extern "C" void kernel_launch(void* const* d_in, const int* in_sizes, int n_in,
                              void* d_out, int out_size) {
    cudaFuncSetAttribute(hgemm_kernel<0>, cudaFuncAttributeMaxDynamicSharedMemorySize, HSMEM);
    cudaFuncSetAttribute(hgemm_kernel<1>, cudaFuncAttributeMaxDynamicSharedMemorySize, HSMEM);
    cudaFuncSetAttribute(hgemm_kernel<4>, cudaFuncAttributeMaxDynamicSharedMemorySize, HSMEM);
    cudaFuncSetAttribute(hgemm64_kernel<2>, cudaFuncAttributeMaxDynamicSharedMemorySize, H64SMEM);
    cudaFuncSetAttribute(hgemm64_kernel<3>, cudaFuncAttributeMaxDynamicSharedMemorySize, H64SMEM);
    cudaFuncSetAttribute(attn2_kernel, cudaFuncAttributeMaxDynamicSharedMemorySize, ATT_SMEM);

    const float* x       = (const float*)d_in[0];
    const float* w_proj[2] = { (const float*)d_in[1], (const float*)d_in[3] };
    const float* b_proj[2] = { (const float*)d_in[2], (const float*)d_in[4] };
    const float* pos[2]    = { (const float*)d_in[5], (const float*)d_in[6] };
    const float* ln1_g = (const float*)d_in[7];
    const float* ln1_b = (const float*)d_in[8];
    const float* wq = (const float*)d_in[9];
    const float* bq = (const float*)d_in[10];
    const float* wk = (const float*)d_in[11];
    const float* bk = (const float*)d_in[12];
    const float* wv = (const float*)d_in[13];
    const float* bv = (const float*)d_in[14];
    const float* wo = (const float*)d_in[15];
    const float* bo = (const float*)d_in[16];
    const float* ln2_g = (const float*)d_in[17];
    const float* ln2_b = (const float*)d_in[18];
    const float* w_ff1 = (const float*)d_in[19];
    const float* b_ff1 = (const float*)d_in[20];
    const float* w_ff2 = (const float*)d_in[21];
    const float* b_ff2 = (const float*)d_in[22];
    const float* ln_g = (const float*)d_in[23];
    const float* ln_b = (const float*)d_in[24];
    const float* w_fus1 = (const float*)d_in[25];
    const float* b_fus1 = (const float*)d_in[26];
    const float* w_fus2 = (const float*)d_in[27];
    const float* b_fus2 = (const float*)d_in[28];

    __half *winh, *qkvh, *s2h, *ffh, *combh, *wth;
    float *tokens, *seq, *bqkv;
    cudaGetSymbolAddress((void**)&winh,   g_winh);
    cudaGetSymbolAddress((void**)&tokens, g_tokens);
    cudaGetSymbolAddress((void**)&seq,    g_seq);
    cudaGetSymbolAddress((void**)&qkvh,   g_qkvh);
    cudaGetSymbolAddress((void**)&s2h,    g_s2h);
    cudaGetSymbolAddress((void**)&ffh,    g_ffh);
    cudaGetSymbolAddress((void**)&combh,  g_combh);
    cudaGetSymbolAddress((void**)&wth,    g_wth);
    cudaGetSymbolAddress((void**)&bqkv,   g_bqkv);

    __half* wt_proj0 = wth;
    __half* wt_proj1 = wth + 16384;
    __half* wt_qkv   = wth + 49152;
    __half* wt_o     = wth + 442368;
    __half* wt_ff1   = wth + 573440;
    __half* wt_ff2   = wth + 1097728;
    __half* wt_fus1  = wth + 1622016;
    __half* wt_fus2  = wth + 1753088;

    WtJobs jobs;
    int nt = 0, nj = 0;
    auto addjob = [&](const float* src, __half* dst, int K, int N) {
        jobs.src[nj] = src; jobs.dst[nj] = dst; jobs.K[nj] = K; jobs.N[nj] = N;
        jobs.t0[nj] = nt; nt += (N / 32) * (K / 32); nj++;
    };
    addjob(w_proj[0], wt_proj0, 64, 256);
    addjob(w_proj[1], wt_proj1, 128, 256);
    for (int li = 0; li < 2; li++) {
        addjob(wq + li * 65536, wt_qkv + li * 196608,          256, 256);
        addjob(wk + li * 65536, wt_qkv + li * 196608 + 65536,  256, 256);
        addjob(wv + li * 65536, wt_qkv + li * 196608 + 131072, 256, 256);
        addjob(wo + li * 65536, wt_o + li * 65536, 256, 256);
        addjob(w_ff1 + li * 262144, wt_ff1 + li * 262144, 256, 1024);
        addjob(w_ff2 + li * 262144, wt_ff2 + li * 262144, 1024, 256);
    }
    addjob(w_fus1, wt_fus1, 512, 256);
    addjob(w_fus2, wt_fus2, 256, 256);
    wt_fused<<<nt, 256>>>(jobs, nj);
    for (int li = 0; li < 2; li++) {
        cudaMemcpyAsync(bqkv + li * 768,       bq + li * 256, 1024, cudaMemcpyDeviceToDevice);
        cudaMemcpyAsync(bqkv + li * 768 + 256, bk + li * 256, 1024, cudaMemcpyDeviceToDevice);
        cudaMemcpyAsync(bqkv + li * 768 + 512, bv + li * 256, 1024, cudaMemcpyDeviceToDevice);
    }

    const int PL[2] = {8, 16}, ST[2] = {4, 8}, EE[2] = {136, 128}, NMX[2] = {34, 16};
    const int MP[2] = {1152, 1024};
    const int MBB[2] = {MB0, MB1}, ROFF[2] = {0, MC0};

    for (int s = 0; s < 2; s++) {
        int pl = PL[s], st = ST[s], E = EE[s], NMAX = NMX[s];
        int plc = pl * CH;
        int BE = BATCH * E;
        { int tot = BE * plc;
          win_kernel<<<(tot + 255) / 256, 256>>>(x, winh, E, pl); }
        gemm(winh, s == 0 ? wt_proj0 : wt_proj1, b_proj[s], tokens, MP[s], HID, plc, 0);
        { int nwarp = NSEQ * NMAX;
          int blocks = (nwarp + 7) / 8;
          if (s == 0) build_seq_ln<0><<<blocks, 256>>>(tokens, pos[s], ln1_g, ln1_b,
                                                       seq, s2h, NMAX, E, pl, st, MBB[s], ROFF[s]);
          else        build_seq_ln<1><<<blocks, 256>>>(tokens, pos[s], ln1_g, ln1_b,
                                                       seq, s2h, NMAX, E, pl, st, MBB[s], ROFF[s]);
        }
    }

    for (int li = 0; li < 2; li++) {
        gemm(s2h, wt_qkv + li * 196608, bqkv + li * 768, qkvh, MTOT, 768, HID, 4);
        attn2_kernel<<<2048, 288, ATT_SMEM>>>(qkvh, s2h);
        gemm64(s2h, wt_o + li * 65536, bo + li * HID, seq, MTOT, HID, 3,
               ln2_g + li * HID, ln2_b + li * HID, s2h);
        gemm(s2h, wt_ff1 + li * 262144, b_ff1 + li * FFD, ffh, MTOT, FFD, HID, 1);
        if (li == 0)
            gemm64(ffh, wt_ff2 + li * 262144, b_ff2 + li * HID, seq, MTOT, FFD, 3,
                   ln1_g + HID, ln1_b + HID, s2h);
        else
            gemm64(ffh, wt_ff2 + li * 262144, b_ff2 + li * HID, seq, MTOT, FFD, 2);
    }

    { int tot = 2 * NSEQ * HID;
      gather2_kernel<<<(tot + 255) / 256, 256>>>(seq, combh); }
    gemm(combh, wt_fus1, b_fus1, s2h, NSEQ, HID, 2 * HID, 1);
    gemm(s2h, wt_fus2, b_fus2, seq, NSEQ, HID, HID, 0);
    ln_final<<<NSEQ / 8, 256>>>(seq, ln_g, ln_b, (float*)d_out);
}